// round 4
// baseline (speedup 1.0000x reference)
#include <cuda_runtime.h>
#include <cuda_bf16.h>
#include <math.h>

// Problem constants
#define BB 4
#define SS 2048
#define DD 2048
#define HH 16
#define DHD 128   // head dim

// ---------------- scratch (device globals; no allocation allowed) -------------
__device__ float g_qh[BB * SS * DD];   // projected Q  [B*S, D]  (heads packed in D)
__device__ float g_kh[BB * SS * DHD];  // projected K  [B*S, DH]
__device__ float g_vh[BB * SS * DHD];  // projected V  [B*S, DH]
__device__ float g_ao[BB * SS * DD];   // attention out, heads merged [B*S, D]

// =============================================================================
// SGEMM: C[M,N] = A[M,K] @ B[K,N] + bias[N]   (all row-major, fp32)
// BM=BN=128, BK=8, 256 threads, 8x8 per-thread tile.
// Global loads for tile k+1 are prefetched into registers while tile k computes.
// =============================================================================
#define GBM 128
#define GBN 128
#define GBK 8

__global__ void __launch_bounds__(256) sgemm_bias_kernel(
    const float* __restrict__ A, const float* __restrict__ B,
    const float* __restrict__ bias, float* __restrict__ C,
    int M, int N, int K)
{
    __shared__ float As[GBK][GBM];   // transposed A tile
    __shared__ float Bs[GBK][GBN];

    const int tid  = threadIdx.x;
    const int brow = blockIdx.y;
    const int bcol = blockIdx.x;

    const int ty = tid >> 4;        // 0..15
    const int tx = tid & 15;        // 0..15

    // A tile load: 128 rows x 8 k ; 2 threads per row, each a float4 along K
    const int a_row = tid >> 1;         // 0..127
    const int a_col = (tid & 1) * 4;    // 0 or 4
    // B tile load: 8 k x 128 n ; 32 threads per k-row, each a float4 along N
    const int b_row = tid >> 5;         // 0..7
    const int b_col = (tid & 31) * 4;   // 0..124

    const float* Aptr = A + (size_t)(brow * GBM + a_row) * K + a_col;
    const float* Bptr = B + (size_t)b_row * N + bcol * GBN + b_col;

    float acc[8][8];
#pragma unroll
    for (int i = 0; i < 8; i++)
#pragma unroll
        for (int j = 0; j < 8; j++) acc[i][j] = 0.0f;

    // prefetch tile 0
    float4 a_pf = *(const float4*)(Aptr);
    float4 b_pf = *(const float4*)(Bptr);

    for (int k0 = 0; k0 < K; k0 += GBK) {
        // commit prefetched tile to smem
        As[a_col + 0][a_row] = a_pf.x;
        As[a_col + 1][a_row] = a_pf.y;
        As[a_col + 2][a_row] = a_pf.z;
        As[a_col + 3][a_row] = a_pf.w;
        *(float4*)(&Bs[b_row][b_col]) = b_pf;
        __syncthreads();

        // prefetch next tile (overlaps with compute below)
        if (k0 + GBK < K) {
            a_pf = *(const float4*)(Aptr + k0 + GBK);
            b_pf = *(const float4*)(Bptr + (size_t)(k0 + GBK) * N);
        }

#pragma unroll
        for (int kk = 0; kk < GBK; kk++) {
            float a[8], b[8];
            *(float4*)(a)     = *(const float4*)(&As[kk][ty * 8]);
            *(float4*)(a + 4) = *(const float4*)(&As[kk][ty * 8 + 4]);
            *(float4*)(b)     = *(const float4*)(&Bs[kk][tx * 8]);
            *(float4*)(b + 4) = *(const float4*)(&Bs[kk][tx * 8 + 4]);
#pragma unroll
            for (int i = 0; i < 8; i++)
#pragma unroll
                for (int j = 0; j < 8; j++)
                    acc[i][j] += a[i] * b[j];
        }
        __syncthreads();
    }

    // epilogue: bias + store
    const int crow = brow * GBM + ty * 8;
    const int ccol = bcol * GBN + tx * 8;
    float bv[8];
    *(float4*)(bv)     = *(const float4*)(bias + ccol);
    *(float4*)(bv + 4) = *(const float4*)(bias + ccol + 4);
#pragma unroll
    for (int i = 0; i < 8; i++) {
        float* crowp = C + (size_t)(crow + i) * N + ccol;
        float4 o0, o1;
        o0.x = acc[i][0] + bv[0]; o0.y = acc[i][1] + bv[1];
        o0.z = acc[i][2] + bv[2]; o0.w = acc[i][3] + bv[3];
        o1.x = acc[i][4] + bv[4]; o1.y = acc[i][5] + bv[5];
        o1.z = acc[i][6] + bv[6]; o1.w = acc[i][7] + bv[7];
        *(float4*)(crowp)     = o0;
        *(float4*)(crowp + 4) = o1;
    }
}

// =============================================================================
// Fused MQA flash attention (fp32).
// grid = (S/BQ, H, B), block = 256.
// Each block: 64 queries of one (b,h), loops over 2048 keys in tiles of 64.
// Q/K/V tiles in dynamic smem (rows padded to 129 floats), scores 64x65.
// Per-thread: query row = tid/4, column set = (tid&3) + 4*i (32 cols of DH=128).
// =============================================================================
#define BQ   64
#define BKV  64
#define KPAD 129
#define SPAD 65

__global__ void __launch_bounds__(256) mqa_attn_kernel(
    const float* __restrict__ qh, const float* __restrict__ kh,
    const float* __restrict__ vh, float* __restrict__ o)
{
    extern __shared__ float sm[];
    float* Qs = sm;                          // BQ  * KPAD
    float* Ks = sm + BQ * KPAD;              // BKV * KPAD  (reused for V)
    float* Ss = sm + 2 * BQ * KPAD;          // BQ  * SPAD

    const int tid = threadIdx.x;
    const int qt  = blockIdx.x;
    const int h   = blockIdx.y;
    const int b   = blockIdx.z;
    const int q0  = qt * BQ;

    const float scale = 0.08838834764831845f;  // 1/sqrt(128)

    const int sr = tid >> 2;        // query row within tile (0..63)
    const int sl = tid & 3;         // column group (0..3)
    const int ty = tid >> 4;        // phase-A micro tile row group
    const int tx = tid & 15;        // phase-A micro tile col group

    // ---- load Q tile ----
    {
        const int c0 = sl * 32;
        const float* src = qh + ((size_t)(b * SS + q0 + sr)) * DD + h * DHD + c0;
#pragma unroll
        for (int i = 0; i < 32; i += 4) {
            float4 v4 = *(const float4*)(src + i);
            float* d = &Qs[sr * KPAD + c0 + i];
            d[0] = v4.x; d[1] = v4.y; d[2] = v4.z; d[3] = v4.w;
        }
    }

    float m_r = -1e30f, l_r = 0.0f;
    float acc[32];
#pragma unroll
    for (int i = 0; i < 32; i++) acc[i] = 0.0f;

    for (int kt = 0; kt < SS / BKV; kt++) {
        const int k0 = kt * BKV;

        // ---- load K tile ----
        {
            const int c0 = sl * 32;
            const float* src = kh + ((size_t)(b * SS + k0 + sr)) * DHD + c0;
#pragma unroll
            for (int i = 0; i < 32; i += 4) {
                float4 v4 = *(const float4*)(src + i);
                float* d = &Ks[sr * KPAD + c0 + i];
                d[0] = v4.x; d[1] = v4.y; d[2] = v4.z; d[3] = v4.w;
            }
        }
        __syncthreads();

        // ---- phase A: S = Q K^T * scale (64x64) ----
        {
            float sacc[4][4];
#pragma unroll
            for (int i = 0; i < 4; i++)
#pragma unroll
                for (int j = 0; j < 4; j++) sacc[i][j] = 0.0f;

#pragma unroll 4
            for (int d = 0; d < DHD; d++) {
                float qv[4], kv[4];
#pragma unroll
                for (int i = 0; i < 4; i++) qv[i] = Qs[(ty * 4 + i) * KPAD + d];
#pragma unroll
                for (int j = 0; j < 4; j++) kv[j] = Ks[(tx * 4 + j) * KPAD + d];
#pragma unroll
                for (int i = 0; i < 4; i++)
#pragma unroll
                    for (int j = 0; j < 4; j++)
                        sacc[i][j] += qv[i] * kv[j];
            }
#pragma unroll
            for (int i = 0; i < 4; i++)
#pragma unroll
                for (int j = 0; j < 4; j++)
                    Ss[(ty * 4 + i) * SPAD + tx * 4 + j] = sacc[i][j] * scale;
        }
        __syncthreads();

        // ---- online softmax on row sr (4 threads cooperate) ----
        {
            float mloc = -1e30f;
#pragma unroll
            for (int i = 0; i < 16; i++)
                mloc = fmaxf(mloc, Ss[sr * SPAD + sl + 4 * i]);
            mloc = fmaxf(mloc, __shfl_xor_sync(0xffffffffu, mloc, 1));
            mloc = fmaxf(mloc, __shfl_xor_sync(0xffffffffu, mloc, 2));
            const float mnew  = fmaxf(m_r, mloc);
            const float alpha = __expf(m_r - mnew);
            float ssum = 0.0f;
#pragma unroll
            for (int i = 0; i < 16; i++) {
                const int idx = sr * SPAD + sl + 4 * i;
                const float p = __expf(Ss[idx] - mnew);
                Ss[idx] = p;
                ssum += p;
            }
            ssum += __shfl_xor_sync(0xffffffffu, ssum, 1);
            ssum += __shfl_xor_sync(0xffffffffu, ssum, 2);
            l_r = l_r * alpha + ssum;
            m_r = mnew;
#pragma unroll
            for (int i = 0; i < 32; i++) acc[i] *= alpha;
        }

        // ---- load V tile into Ks buffer (phase A is done; safe) ----
        {
            const int c0 = sl * 32;
            const float* src = vh + ((size_t)(b * SS + k0 + sr)) * DHD + c0;
#pragma unroll
            for (int i = 0; i < 32; i += 4) {
                float4 v4 = *(const float4*)(src + i);
                float* d = &Ks[sr * KPAD + c0 + i];
                d[0] = v4.x; d[1] = v4.y; d[2] = v4.z; d[3] = v4.w;
            }
        }
        __syncthreads();

        // ---- phase C: O += P @ V ----
#pragma unroll 2
        for (int j = 0; j < BKV; j++) {
            const float p = Ss[sr * SPAD + j];
            const float* vrow = &Ks[j * KPAD + sl];
#pragma unroll
            for (int i = 0; i < 32; i++)
                acc[i] += p * vrow[4 * i];
        }
        __syncthreads();
    }

    // ---- normalize + write merged-head output ----
    const float inv = 1.0f / l_r;
    float* dst = o + ((size_t)(b * SS + q0 + sr)) * DD + h * DHD;
#pragma unroll
    for (int i = 0; i < 32; i++)
        dst[sl + 4 * i] = acc[i] * inv;
}

// =============================================================================
// launch
// =============================================================================
extern "C" void kernel_launch(void* const* d_in, const int* in_sizes, int n_in,
                              void* d_out, int out_size)
{
    const float* q  = (const float*)d_in[0];
    const float* k  = (const float*)d_in[1];
    const float* v  = (const float*)d_in[2];
    const float* Wq = (const float*)d_in[3];
    const float* bq = (const float*)d_in[4];
    const float* Wk = (const float*)d_in[5];
    const float* bk = (const float*)d_in[6];
    const float* Wv = (const float*)d_in[7];
    const float* bv = (const float*)d_in[8];
    const float* Wo = (const float*)d_in[9];
    const float* bo = (const float*)d_in[10];
    float* out = (float*)d_out;

    float *qh_p, *kh_p, *vh_p, *ao_p;
    cudaGetSymbolAddress((void**)&qh_p, g_qh);
    cudaGetSymbolAddress((void**)&kh_p, g_kh);
    cudaGetSymbolAddress((void**)&vh_p, g_vh);
    cudaGetSymbolAddress((void**)&ao_p, g_ao);

    const int M = BB * SS;   // 8192

    // Q projection: [8192,2048] @ [2048,2048]
    {
        dim3 grid(DD / GBN, M / GBM);
        sgemm_bias_kernel<<<grid, 256>>>(q, Wq, bq, qh_p, M, DD, DD);
    }
    // K / V projections: [8192,2048] @ [2048,128]
    {
        dim3 grid(DHD / GBN, M / GBM);
        sgemm_bias_kernel<<<grid, 256>>>(k, Wk, bk, kh_p, M, DHD, DD);
        sgemm_bias_kernel<<<grid, 256>>>(v, Wv, bv, vh_p, M, DHD, DD);
    }
    // Fused attention
    {
        const int smem_bytes = (2 * BQ * KPAD + BQ * SPAD) * (int)sizeof(float);
        cudaFuncSetAttribute(mqa_attn_kernel,
                             cudaFuncAttributeMaxDynamicSharedMemorySize,
                             smem_bytes);
        dim3 grid(SS / BQ, HH, BB);
        mqa_attn_kernel<<<grid, 256, smem_bytes>>>(qh_p, kh_p, vh_p, ao_p);
    }
    // Output projection: [8192,2048] @ [2048,2048]
    {
        dim3 grid(DD / GBN, M / GBM);
        sgemm_bias_kernel<<<grid, 256>>>(ao_p, Wo, bo, out, M, DD, DD);
    }
}

// round 6
// speedup vs baseline: 1.2541x; 1.2541x over previous
#include <cuda_runtime.h>
#include <cuda_bf16.h>
#include <math.h>
#include <stdint.h>

// Problem constants
#define BB 4
#define SS 2048
#define DD 2048
#define HH 16
#define DHD 128   // head dim

// ---------------- scratch (device globals; no allocation allowed) -------------
__device__ float g_qh[BB * SS * DD];   // projected Q  [B*S, D]
__device__ float g_kh[BB * SS * DHD];  // projected K  [B*S, DH]
__device__ float g_vh[BB * SS * DHD];  // projected V  [B*S, DH]
__device__ float g_ao[BB * SS * DD];   // attention out, heads merged [B*S, D]
__device__ __nv_bfloat16 g_ahi[BB * SS * DD];  // activation split hi  [M,K]
__device__ __nv_bfloat16 g_alo[BB * SS * DD];  // activation split lo  [M,K]
__device__ __nv_bfloat16 g_whi[DD * DD];       // weight^T split hi    [N,K]
__device__ __nv_bfloat16 g_wlo[DD * DD];       // weight^T split lo    [N,K]

// ============================ PTX helpers ====================================
__device__ __forceinline__ uint32_t smem_u32(const void* p) {
    uint32_t a;
    asm("{ .reg .u64 t; cvta.to.shared.u64 t, %1; cvt.u32.u64 %0, t; }"
        : "=r"(a) : "l"(p));
    return a;
}
#define CP_ASYNC16(sa, gp) \
    asm volatile("cp.async.cg.shared.global [%0], [%1], 16;" :: "r"(sa), "l"(gp))
#define CP_COMMIT() asm volatile("cp.async.commit_group;" ::: "memory")
#define CP_WAIT1()  asm volatile("cp.async.wait_group 1;" ::: "memory")
#define CP_WAIT0()  asm volatile("cp.async.wait_group 0;" ::: "memory")

#define LDSM4(r0, r1, r2, r3, addr) \
    asm volatile("ldmatrix.sync.aligned.m8n8.x4.shared.b16 {%0,%1,%2,%3}, [%4];" \
                 : "=r"(r0), "=r"(r1), "=r"(r2), "=r"(r3) : "r"(addr))

#define MMA16816(d, a, b0, b1) \
    asm volatile("mma.sync.aligned.m16n8k16.row.col.f32.bf16.bf16.f32 " \
                 "{%0,%1,%2,%3}, {%4,%5,%6,%7}, {%8,%9}, {%0,%1,%2,%3};" \
                 : "+f"((d)[0]), "+f"((d)[1]), "+f"((d)[2]), "+f"((d)[3]) \
                 : "r"((a)[0]), "r"((a)[1]), "r"((a)[2]), "r"((a)[3]), \
                   "r"(b0), "r"(b1))

// ============================ split / transpose kernels ======================
__global__ void __launch_bounds__(256) split_act_kernel(
    const float* __restrict__ x, __nv_bfloat16* __restrict__ hi,
    __nv_bfloat16* __restrict__ lo, int n)
{
    int i = (blockIdx.x * 256 + threadIdx.x) * 4;
    if (i >= n) return;
    float4 v = *(const float4*)(x + i);
    __nv_bfloat16 h[4], l[4];
    float vv[4] = {v.x, v.y, v.z, v.w};
#pragma unroll
    for (int j = 0; j < 4; j++) {
        h[j] = __float2bfloat16(vv[j]);
        l[j] = __float2bfloat16(vv[j] - __bfloat162float(h[j]));
    }
    *(uint2*)(hi + i) = *(uint2*)h;
    *(uint2*)(lo + i) = *(uint2*)l;
}

// W [K,N] row-major -> WT hi/lo [N,K] bf16
__global__ void __launch_bounds__(256) split_wT_kernel(
    const float* __restrict__ W, __nv_bfloat16* __restrict__ hiT,
    __nv_bfloat16* __restrict__ loT, int K, int N)
{
    __shared__ float t[32][33];
    const int tx = threadIdx.x, ty = threadIdx.y;   // (32, 8)
    const int n = blockIdx.x * 32 + tx;
    const int k0 = blockIdx.y * 32;
#pragma unroll
    for (int i = 0; i < 32; i += 8)
        t[ty + i][tx] = W[(size_t)(k0 + ty + i) * N + n];
    __syncthreads();
    const int nn = blockIdx.x * 32 + ty;
    const int kk = k0 + tx;
#pragma unroll
    for (int i = 0; i < 32; i += 8) {
        float v = t[tx][ty + i];
        __nv_bfloat16 h = __float2bfloat16(v);
        hiT[(size_t)(nn + i) * K + kk] = h;
        loT[(size_t)(nn + i) * K + kk] = __float2bfloat16(v - __bfloat162float(h));
    }
}

// ============================ HMMA split-bf16 GEMM ===========================
// C[M,N] = A[M,K] @ W[K,N] + bias via A(hi/lo)[M,K], B=W^T(hi/lo)[N,K] bf16.
// CTA tile 128x128, K chunk 32, cp.async double buffer, mma.sync.m16n8k16.
// Warps: 4 (m) x 2 (n); each warp 32x64 = 2 m-tiles x 8 n-tiles.
// smem tile layout per operand: 128 rows x 64B, 16B chunk index swizzled by
// (chunk ^ ((row>>1)&3)) -> conflict-free ldmatrix phases.
#define MT 128
#define NT 128
#define KC 32
#define STG 32768      // bytes per stage: 4 tiles x 8KB
#define GSMEM (2 * STG)

__global__ void __launch_bounds__(256) gemm_bf16s_mma(
    const __nv_bfloat16* __restrict__ Ahi, const __nv_bfloat16* __restrict__ Alo,
    const __nv_bfloat16* __restrict__ Bhi, const __nv_bfloat16* __restrict__ Blo,
    const float* __restrict__ bias, float* __restrict__ C,
    int M, int N, int K)
{
    extern __shared__ char smem[];
    const uint32_t sb = smem_u32(smem);
    const int tid  = threadIdx.x;
    const int lane = tid & 31;
    const int wid  = tid >> 5;
    const int warp_m = wid & 3;   // 0..3 -> 32 rows each
    const int warp_n = wid >> 2;  // 0..1 -> 64 cols each
    const int m0 = blockIdx.y * MT;
    const int n0 = blockIdx.x * NT;

    float acc[2][8][4];
#pragma unroll
    for (int i = 0; i < 2; i++)
#pragma unroll
        for (int j = 0; j < 8; j++)
#pragma unroll
            for (int c = 0; c < 4; c++) acc[i][j][c] = 0.0f;

    const int nch = K / KC;

    // ---- chunk loader: 4 tiles (Ahi,Alo,Bhi,Blo), each 128 rows x 32 bf16 ----
    auto load_chunk = [&](int ch, int st) {
        const uint32_t s0 = sb + st * STG;
        const int kc = ch * KC;
#pragma unroll
        for (int i = 0; i < 8; i++) {
            const int g    = tid + i * 256;   // 0..2047
            const int tile = g >> 9;          // 0..3
            const int idx  = g & 511;
            const int row  = idx >> 2;
            const int c    = idx & 3;
            const int pc   = c ^ ((row >> 1) & 3);
            const uint32_t so = s0 + tile * 8192 + row * 64 + pc * 16;
            const __nv_bfloat16* gp;
            if (tile == 0)      gp = Ahi + (size_t)(m0 + row) * K + kc + c * 8;
            else if (tile == 1) gp = Alo + (size_t)(m0 + row) * K + kc + c * 8;
            else if (tile == 2) gp = Bhi + (size_t)(n0 + row) * K + kc + c * 8;
            else                gp = Blo + (size_t)(n0 + row) * K + kc + c * 8;
            CP_ASYNC16(so, gp);
        }
        CP_COMMIT();
    };

    load_chunk(0, 0);

    for (int ch = 0; ch < nch; ch++) {
        const int st = ch & 1;
        const bool more = (ch + 1) < nch;
        if (more) load_chunk(ch + 1, st ^ 1);
        if (more) { CP_WAIT1(); } else { CP_WAIT0(); }
        __syncthreads();

        const uint32_t s0 = sb + st * STG;
#pragma unroll
        for (int ks = 0; ks < 2; ks++) {
            // ---- A fragments (hi & lo) ----
            uint32_t ahi[2][4], alo[2][4];
            const int arow_off = (lane & 7) + ((lane >> 3) & 1) * 8;
            const int akc = ks * 2 + (lane >> 4);
#pragma unroll
            for (int mt = 0; mt < 2; mt++) {
                const int mrow = warp_m * 32 + mt * 16 + arow_off;
                const int pc = akc ^ ((mrow >> 1) & 3);
                const uint32_t ad = s0 + mrow * 64 + pc * 16;
                LDSM4(ahi[mt][0], ahi[mt][1], ahi[mt][2], ahi[mt][3], ad);
                LDSM4(alo[mt][0], alo[mt][1], alo[mt][2], alo[mt][3], ad + 8192);
            }
            // ---- B fragments (hi & lo): 4 x ldmatrix.x4 -> 8 n-tiles ----
            uint32_t bhi[8][2], blo[8][2];
            const int brow_off = (lane & 7) + ((lane >> 4) & 1) * 8;
            const int bkc = ks * 2 + ((lane >> 3) & 1);
#pragma unroll
            for (int j = 0; j < 4; j++) {
                const int nrow = warp_n * 64 + j * 16 + brow_off;
                const int pc = bkc ^ ((nrow >> 1) & 3);
                const uint32_t bd = s0 + 16384 + nrow * 64 + pc * 16;
                uint32_t r0, r1, r2, r3;
                LDSM4(r0, r1, r2, r3, bd);
                bhi[2 * j][0] = r0; bhi[2 * j][1] = r1;
                bhi[2 * j + 1][0] = r2; bhi[2 * j + 1][1] = r3;
                LDSM4(r0, r1, r2, r3, bd + 8192);
                blo[2 * j][0] = r0; blo[2 * j][1] = r1;
                blo[2 * j + 1][0] = r2; blo[2 * j + 1][1] = r3;
            }
            // ---- 3-product split MMAs ----
#pragma unroll
            for (int mt = 0; mt < 2; mt++)
#pragma unroll
                for (int nt = 0; nt < 8; nt++) {
                    MMA16816(acc[mt][nt], ahi[mt], bhi[nt][0], bhi[nt][1]);
                    MMA16816(acc[mt][nt], ahi[mt], blo[nt][0], blo[nt][1]);
                    MMA16816(acc[mt][nt], alo[mt], bhi[nt][0], bhi[nt][1]);
                }
        }
        __syncthreads();
    }

    // ---- epilogue: bias + direct float2 stores ----
    const int r0 = lane >> 2;
    const int cc = (lane & 3) * 2;
    const int mbase = m0 + warp_m * 32;
    const int nbase = n0 + warp_n * 64;
#pragma unroll
    for (int nt = 0; nt < 8; nt++) {
        const int col = nbase + nt * 8 + cc;
        const float2 bv = *(const float2*)(bias + col);
#pragma unroll
        for (int mt = 0; mt < 2; mt++) {
            const int row_a = mbase + mt * 16 + r0;
            float2 v0, v1;
            v0.x = acc[mt][nt][0] + bv.x; v0.y = acc[mt][nt][1] + bv.y;
            v1.x = acc[mt][nt][2] + bv.x; v1.y = acc[mt][nt][3] + bv.y;
            *(float2*)(C + (size_t)row_a * N + col) = v0;
            *(float2*)(C + (size_t)(row_a + 8) * N + col) = v1;
        }
    }
}

// =============================================================================
// Fused MQA flash attention (fp32) — unchanged.
// =============================================================================
#define BQ   64
#define BKV  64
#define KPAD 129
#define SPAD 65

__global__ void __launch_bounds__(256) mqa_attn_kernel(
    const float* __restrict__ qh, const float* __restrict__ kh,
    const float* __restrict__ vh, float* __restrict__ o)
{
    extern __shared__ float sm[];
    float* Qs = sm;
    float* Ks = sm + BQ * KPAD;
    float* Ss = sm + 2 * BQ * KPAD;

    const int tid = threadIdx.x;
    const int qt  = blockIdx.x;
    const int h   = blockIdx.y;
    const int b   = blockIdx.z;
    const int q0  = qt * BQ;

    const float scale = 0.08838834764831845f;

    const int sr = tid >> 2;
    const int sl = tid & 3;
    const int ty = tid >> 4;
    const int tx = tid & 15;

    {
        const int c0 = sl * 32;
        const float* src = qh + ((size_t)(b * SS + q0 + sr)) * DD + h * DHD + c0;
#pragma unroll
        for (int i = 0; i < 32; i += 4) {
            float4 v4 = *(const float4*)(src + i);
            float* d = &Qs[sr * KPAD + c0 + i];
            d[0] = v4.x; d[1] = v4.y; d[2] = v4.z; d[3] = v4.w;
        }
    }

    float m_r = -1e30f, l_r = 0.0f;
    float acc[32];
#pragma unroll
    for (int i = 0; i < 32; i++) acc[i] = 0.0f;

    for (int kt = 0; kt < SS / BKV; kt++) {
        const int k0 = kt * BKV;
        {
            const int c0 = sl * 32;
            const float* src = kh + ((size_t)(b * SS + k0 + sr)) * DHD + c0;
#pragma unroll
            for (int i = 0; i < 32; i += 4) {
                float4 v4 = *(const float4*)(src + i);
                float* d = &Ks[sr * KPAD + c0 + i];
                d[0] = v4.x; d[1] = v4.y; d[2] = v4.z; d[3] = v4.w;
            }
        }
        __syncthreads();

        {
            float sacc[4][4];
#pragma unroll
            for (int i = 0; i < 4; i++)
#pragma unroll
                for (int j = 0; j < 4; j++) sacc[i][j] = 0.0f;

#pragma unroll 4
            for (int d = 0; d < DHD; d++) {
                float qv[4], kv[4];
#pragma unroll
                for (int i = 0; i < 4; i++) qv[i] = Qs[(ty * 4 + i) * KPAD + d];
#pragma unroll
                for (int j = 0; j < 4; j++) kv[j] = Ks[(tx * 4 + j) * KPAD + d];
#pragma unroll
                for (int i = 0; i < 4; i++)
#pragma unroll
                    for (int j = 0; j < 4; j++)
                        sacc[i][j] += qv[i] * kv[j];
            }
#pragma unroll
            for (int i = 0; i < 4; i++)
#pragma unroll
                for (int j = 0; j < 4; j++)
                    Ss[(ty * 4 + i) * SPAD + tx * 4 + j] = sacc[i][j] * scale;
        }
        __syncthreads();

        {
            float mloc = -1e30f;
#pragma unroll
            for (int i = 0; i < 16; i++)
                mloc = fmaxf(mloc, Ss[sr * SPAD + sl + 4 * i]);
            mloc = fmaxf(mloc, __shfl_xor_sync(0xffffffffu, mloc, 1));
            mloc = fmaxf(mloc, __shfl_xor_sync(0xffffffffu, mloc, 2));
            const float mnew  = fmaxf(m_r, mloc);
            const float alpha = __expf(m_r - mnew);
            float ssum = 0.0f;
#pragma unroll
            for (int i = 0; i < 16; i++) {
                const int idx = sr * SPAD + sl + 4 * i;
                const float p = __expf(Ss[idx] - mnew);
                Ss[idx] = p;
                ssum += p;
            }
            ssum += __shfl_xor_sync(0xffffffffu, ssum, 1);
            ssum += __shfl_xor_sync(0xffffffffu, ssum, 2);
            l_r = l_r * alpha + ssum;
            m_r = mnew;
#pragma unroll
            for (int i = 0; i < 32; i++) acc[i] *= alpha;
        }

        {
            const int c0 = sl * 32;
            const float* src = vh + ((size_t)(b * SS + k0 + sr)) * DHD + c0;
#pragma unroll
            for (int i = 0; i < 32; i += 4) {
                float4 v4 = *(const float4*)(src + i);
                float* d = &Ks[sr * KPAD + c0 + i];
                d[0] = v4.x; d[1] = v4.y; d[2] = v4.z; d[3] = v4.w;
            }
        }
        __syncthreads();

#pragma unroll 2
        for (int j = 0; j < BKV; j++) {
            const float p = Ss[sr * SPAD + j];
            const float* vrow = &Ks[j * KPAD + sl];
#pragma unroll
            for (int i = 0; i < 32; i++)
                acc[i] += p * vrow[4 * i];
        }
        __syncthreads();
    }

    const float inv = 1.0f / l_r;
    float* dst = o + ((size_t)(b * SS + q0 + sr)) * DD + h * DHD;
#pragma unroll
    for (int i = 0; i < 32; i++)
        dst[sl + 4 * i] = acc[i] * inv;
}

// =============================================================================
// launch
// =============================================================================
extern "C" void kernel_launch(void* const* d_in, const int* in_sizes, int n_in,
                              void* d_out, int out_size)
{
    const float* q  = (const float*)d_in[0];
    const float* k  = (const float*)d_in[1];
    const float* v  = (const float*)d_in[2];
    const float* Wq = (const float*)d_in[3];
    const float* bq = (const float*)d_in[4];
    const float* Wk = (const float*)d_in[5];
    const float* bk = (const float*)d_in[6];
    const float* Wv = (const float*)d_in[7];
    const float* bv = (const float*)d_in[8];
    const float* Wo = (const float*)d_in[9];
    const float* bo = (const float*)d_in[10];
    float* out = (float*)d_out;

    float *qh_p, *kh_p, *vh_p, *ao_p;
    __nv_bfloat16 *ahi_p, *alo_p, *whi_p, *wlo_p;
    cudaGetSymbolAddress((void**)&qh_p, g_qh);
    cudaGetSymbolAddress((void**)&kh_p, g_kh);
    cudaGetSymbolAddress((void**)&vh_p, g_vh);
    cudaGetSymbolAddress((void**)&ao_p, g_ao);
    cudaGetSymbolAddress((void**)&ahi_p, g_ahi);
    cudaGetSymbolAddress((void**)&alo_p, g_alo);
    cudaGetSymbolAddress((void**)&whi_p, g_whi);
    cudaGetSymbolAddress((void**)&wlo_p, g_wlo);

    const int M = BB * SS;            // 8192
    const int NE = M * DD;            // activation elements

    cudaFuncSetAttribute(gemm_bf16s_mma,
                         cudaFuncAttributeMaxDynamicSharedMemorySize, GSMEM);

    const dim3 big_grid(DD / NT, M / MT);     // (16, 64)
    const dim3 kv_grid(DHD / NT, M / MT);     // (1, 64)
    const int split_blocks = (NE / 4 + 255) / 256;

    // ---- Q projection ----
    split_act_kernel<<<split_blocks, 256>>>(q, ahi_p, alo_p, NE);
    split_wT_kernel<<<dim3(DD / 32, DD / 32), dim3(32, 8)>>>(Wq, whi_p, wlo_p, DD, DD);
    gemm_bf16s_mma<<<big_grid, 256, GSMEM>>>(ahi_p, alo_p, whi_p, wlo_p,
                                             bq, qh_p, M, DD, DD);
    // ---- K projection ----
    split_act_kernel<<<split_blocks, 256>>>(k, ahi_p, alo_p, NE);
    split_wT_kernel<<<dim3(DHD / 32, DD / 32), dim3(32, 8)>>>(Wk, whi_p, wlo_p, DD, DHD);
    gemm_bf16s_mma<<<kv_grid, 256, GSMEM>>>(ahi_p, alo_p, whi_p, wlo_p,
                                            bk, kh_p, M, DHD, DD);
    // ---- V projection ----
    split_act_kernel<<<split_blocks, 256>>>(v, ahi_p, alo_p, NE);
    split_wT_kernel<<<dim3(DHD / 32, DD / 32), dim3(32, 8)>>>(Wv, whi_p, wlo_p, DD, DHD);
    gemm_bf16s_mma<<<kv_grid, 256, GSMEM>>>(ahi_p, alo_p, whi_p, wlo_p,
                                            bv, vh_p, M, DHD, DD);
    // ---- Attention ----
    {
        const int smem_bytes = (2 * BQ * KPAD + BQ * SPAD) * (int)sizeof(float);
        cudaFuncSetAttribute(mqa_attn_kernel,
                             cudaFuncAttributeMaxDynamicSharedMemorySize, smem_bytes);
        dim3 grid(SS / BQ, HH, BB);
        mqa_attn_kernel<<<grid, 256, smem_bytes>>>(qh_p, kh_p, vh_p, ao_p);
    }
    // ---- Output projection ----
    split_act_kernel<<<split_blocks, 256>>>(ao_p, ahi_p, alo_p, NE);
    split_wT_kernel<<<dim3(DD / 32, DD / 32), dim3(32, 8)>>>(Wo, whi_p, wlo_p, DD, DD);
    gemm_bf16s_mma<<<big_grid, 256, GSMEM>>>(ahi_p, alo_p, whi_p, wlo_p,
                                             bo, out, M, DD, DD);
}